// round 11
// baseline (speedup 1.0000x reference)
#include <cuda_runtime.h>
#include <cuda_fp16.h>
#include <cstdint>

#define NSP 4096      // H*W*D = 16^3
#define CCH 256
#define NHEADS 8
#define HD 32
#define QB 128
#define KB 128

// scratch, all channel-pair-interleaved half2 words: X2[c/2][n] = half2(X[c],X[c+1])
__device__ uint32_t g_y2[(CCH / 2) * NSP];
__device__ uint32_t g_qkv2[(3 * CCH / 2) * NSP];   // Q rows pre-scaled by hd^-.5*log2e
__device__ uint32_t g_att2[(CCH / 2) * NSP];
// weights as half2 k-pairs: W2[m][k/2]
__device__ uint32_t g_wq2[3 * CCH * (CCH / 2)];
__device__ uint32_t g_wp2[CCH * (CCH / 2)];

// ---------------------------------------------------------------------------
__device__ __forceinline__ uint32_t smem_u32(const void* p) {
    uint32_t a;
    asm("{ .reg .u64 t; cvta.to.shared.u64 t, %1; cvt.u32.u64 %0, t; }" : "=r"(a) : "l"(p));
    return a;
}
__device__ __forceinline__ void cp16(uint32_t saddr, const void* g) {
    asm volatile("cp.async.cg.shared.global [%0], [%1], 16;" :: "r"(saddr), "l"(g));
}
#define CP_COMMIT() asm volatile("cp.async.commit_group;" ::: "memory")
#define CP_WAIT0()  asm volatile("cp.async.wait_group 0;" ::: "memory")

__device__ __forceinline__ void mmaf16(float c[4], const uint32_t a[4],
                                       uint32_t b0, uint32_t b1) {
    asm("mma.sync.aligned.m16n8k16.row.col.f32.f16.f16.f32 "
        "{%0,%1,%2,%3}, {%4,%5,%6,%7}, {%8,%9}, {%0,%1,%2,%3};"
        : "+f"(c[0]), "+f"(c[1]), "+f"(c[2]), "+f"(c[3])
        : "r"(a[0]), "r"(a[1]), "r"(a[2]), "r"(a[3]), "r"(b0), "r"(b1));
}
__device__ __forceinline__ uint32_t packh2(float lo, float hi) {
    __half2 h = __float22half2_rn(make_float2(lo, hi));
    return *reinterpret_cast<uint32_t*>(&h);
}
__device__ __forceinline__ uint32_t ex2h2(uint32_t x) {
    uint32_t r; asm("ex2.approx.f16x2 %0, %1;" : "=r"(r) : "r"(x)); return r;
}
__device__ __forceinline__ uint32_t prmt(uint32_t a, uint32_t b, uint32_t sel) {
    uint32_t d; asm("prmt.b32 %0, %1, %2, %3;" : "=r"(d) : "r"(a), "r"(b), "r"(sel)); return d;
}

// ---------------------------------------------------------------------------
// Kernel 1: depthwise conv + InstanceNorm (blocks 0..127, 2 channels each),
// PLUS weight fp32->half2 pre-conversion on spare blocks 128..147 (free:
// those SMs would be idle during the conv anyway).
// ---------------------------------------------------------------------------
__global__ __launch_bounds__(256) void conv_in_kernel(
    const float* __restrict__ x, const float* __restrict__ wdw,
    const float* __restrict__ bdw, uint32_t* __restrict__ y2,
    const float* __restrict__ wq, const float* __restrict__ wp,
    uint32_t* __restrict__ wq2, uint32_t* __restrict__ wp2)
{
    const int tid = threadIdx.x;

    if (blockIdx.x >= 128) {
        // weight prep on 20 spare blocks
        const int idx = (blockIdx.x - 128) * 256 + tid;
        const int STR = 20 * 256;
        const int NQ = 3 * CCH * (CCH / 2);
        for (int i = idx; i < NQ; i += STR) {
            float2 f = *(const float2*)(wq + 2 * i);
            wq2[i] = packh2(f.x, f.y);
        }
        const int NP = CCH * (CCH / 2);
        for (int i = idx; i < NP; i += STR) {
            float2 f = *(const float2*)(wp + 2 * i);
            wp2[i] = packh2(f.x, f.y);
        }
        return;
    }

    const int cp = blockIdx.x;       // channel pair
    __shared__ float xs[NSP];
    __shared__ float red[512];

    const int w  = tid >> 4;
    const int dd = tid & 15;

    float prev[16];
    float out[16];

    for (int s = 0; s < 2; ++s) {
        const int c = 2 * cp + s;
        __syncthreads();
        const float4* xg = (const float4*)(x + (size_t)c * NSP);
        float4* xs4 = (float4*)xs;
        #pragma unroll
        for (int i = 0; i < 4; ++i) xs4[tid + 256 * i] = xg[tid + 256 * i];

        float wr[27];
        #pragma unroll
        for (int i = 0; i < 27; ++i) wr[i] = wdw[c * 27 + i];
        const float bias = bdw[c];
        __syncthreads();

        float sm = 0.f, s2 = 0.f;
        for (int hh = 0; hh < 16; ++hh) {
            float acc = bias;
            #pragma unroll
            for (int i = 0; i < 3; ++i) {
                int ih = hh + i - 1;
                if ((unsigned)ih < 16u) {
                    #pragma unroll
                    for (int j = 0; j < 3; ++j) {
                        int iw = w + j - 1;
                        if ((unsigned)iw < 16u) {
                            #pragma unroll
                            for (int k = 0; k < 3; ++k) {
                                int id = dd + k - 1;
                                if ((unsigned)id < 16u)
                                    acc = fmaf(xs[ih * 256 + iw * 16 + id], wr[i * 9 + j * 3 + k], acc);
                            }
                        }
                    }
                }
            }
            out[hh] = acc;
            sm += acc;
            s2 = fmaf(acc, acc, s2);
        }

        red[tid] = sm; red[256 + tid] = s2;
        __syncthreads();
        for (int st = 128; st > 0; st >>= 1) {
            if (tid < st) { red[tid] += red[tid + st]; red[256 + tid] += red[256 + tid + st]; }
            __syncthreads();
        }
        const float mean = red[0] * (1.0f / NSP);
        const float var  = red[256] * (1.0f / NSP) - mean * mean;
        const float rs   = rsqrtf(var + 1e-5f);

        if (s == 0) {
            for (int hh = 0; hh < 16; ++hh) prev[hh] = (out[hh] - mean) * rs;
        } else {
            for (int hh = 0; hh < 16; ++hh)
                y2[(size_t)cp * NSP + hh * 256 + tid] = packh2(prev[hh], (out[hh] - mean) * rs);
        }
    }
}

// ---------------------------------------------------------------------------
// Kernel 2/4: fp16 GEMM, BM=64, BN=64, full K=256 single-stage, 128 threads
// (4 warps, 2m x 2n). Both A (pre-converted weights) and B staged by cp.async.
// HOUT: half2 pair-interleaved C with per-row scale (qsc for rows<256);
// else fp32 out. smem words: As[64][132] + Bs[128][72] = 70656 B.
// Grids of 256/768 CTAs -> ~2 CTAs/SM co-residency hides the latency chain.
// ---------------------------------------------------------------------------
template<bool HOUT>
__global__ __launch_bounds__(128) void gemm_h2(
    const uint32_t* __restrict__ A2, const uint32_t* __restrict__ B2,
    const float* __restrict__ bias, void* __restrict__ Cout,
    int N, float qsc)
{
    extern __shared__ uint32_t gsm[];
    auto As = (uint32_t(*)[132])gsm;              // [64][132]
    auto Bs = (uint32_t(*)[72])(gsm + 64 * 132);  // [128][72]

    const int tid  = threadIdx.x;
    const int w    = tid >> 5;
    const int lane = tid & 31;
    const int gid  = lane >> 2;
    const int tig  = lane & 3;
    const int wm   = w >> 1;
    const int wn   = w & 1;
    const int bm   = blockIdx.y * 64;
    const int bn   = blockIdx.x * 64;

    // stage A: half2 k-pairs, row r, half hf (64 words each)
    {
        const int r = tid >> 1, hf = tid & 1;
        const uint32_t* ar = A2 + (size_t)(bm + r) * 128 + hf * 64;
        #pragma unroll
        for (int p = 0; p < 16; ++p)
            cp16(smem_u32(&As[r][hf * 64 + p * 4]), ar + p * 4);
    }
    // stage B: k-pair row tid, 64 words
    {
        const uint32_t* br = B2 + (size_t)tid * N + bn;
        #pragma unroll
        for (int p = 0; p < 16; ++p)
            cp16(smem_u32(&Bs[tid][p * 4]), br + p * 4);
    }
    CP_COMMIT();
    CP_WAIT0();
    __syncthreads();

    float acc[2][4][4] = {};
    #pragma unroll
    for (int ks = 0; ks < 16; ++ks) {
        uint32_t a[2][4];
        #pragma unroll
        for (int u = 0; u < 2; ++u) {
            const int mb = wm * 32 + u * 16 + gid;
            a[u][0] = As[mb][ks * 8 + tig];
            a[u][1] = As[mb + 8][ks * 8 + tig];
            a[u][2] = As[mb][ks * 8 + tig + 4];
            a[u][3] = As[mb + 8][ks * 8 + tig + 4];
        }
        #pragma unroll
        for (int nt = 0; nt < 4; ++nt) {
            const int col = wn * 32 + nt * 8 + gid;
            uint32_t b0 = Bs[ks * 8 + tig][col];
            uint32_t b1 = Bs[ks * 8 + tig + 4][col];
            mmaf16(acc[0][nt], a[0], b0, b1);
            mmaf16(acc[1][nt], a[1], b0, b1);
        }
    }
    __syncthreads();

    if (HOUT) {
        const float sc = (bm < 256) ? qsc : 1.0f;
        uint32_t* Cs32 = gsm;            // [64][36] words (72 halves/row)
        #pragma unroll
        for (int u = 0; u < 2; ++u) {
            const int r0 = wm * 32 + u * 16 + gid;
            const float bv0 = bias[bm + r0];
            const float bv1 = bias[bm + r0 + 8];
            #pragma unroll
            for (int nt = 0; nt < 4; ++nt) {
                const int wc = wn * 16 + nt * 4 + tig;
                Cs32[r0 * 36 + wc]       = packh2((acc[u][nt][0] + bv0) * sc,
                                                  (acc[u][nt][1] + bv0) * sc);
                Cs32[(r0 + 8) * 36 + wc] = packh2((acc[u][nt][2] + bv1) * sc,
                                                  (acc[u][nt][3] + bv1) * sc);
            }
        }
        __syncthreads();
        const unsigned short* Ch = (const unsigned short*)gsm;
        uint32_t* C2 = (uint32_t*)Cout;
        const int n  = tid & 63;
        const int rg = tid >> 6;
        #pragma unroll
        for (int p = 0; p < 16; ++p) {
            const int r = rg * 16 + p;
            uint32_t lo = Ch[(2 * r) * 72 + n];
            uint32_t hi = Ch[(2 * r + 1) * 72 + n];
            C2[(size_t)((bm >> 1) + r) * N + bn + n] = lo | (hi << 16);
        }
    } else {
        float* C = (float*)Cout;
        #pragma unroll
        for (int u = 0; u < 2; ++u) {
            const int m0 = bm + wm * 32 + u * 16 + gid;
            const float bv0 = bias[m0];
            const float bv1 = bias[m0 + 8];
            #pragma unroll
            for (int nt = 0; nt < 4; ++nt) {
                const int n = bn + wn * 32 + nt * 8 + tig * 2;
                *(float2*)(C + (size_t)m0 * N + n) =
                    make_float2(acc[u][nt][0] + bv0, acc[u][nt][1] + bv0);
                *(float2*)(C + (size_t)(m0 + 8) * N + n) =
                    make_float2(acc[u][nt][2] + bv1, acc[u][nt][3] + bv1);
            }
        }
    }
}

// ---------------------------------------------------------------------------
// Kernel 3: fp16 flash attention, QB=128, 4 warps (32 q-rows each), grid
// (32, 8) = 256 CTAs -> 2 CTAs/SM co-residency. Per-warp math identical to
// the verified round-10 kernel (reg-P fusion, ex2.f16x2, l via ones-MMA).
// smem words: Ksm[2][16][136] + Vsm[2][32][68] + Psm[4][32][36] = 53248 B.
// ---------------------------------------------------------------------------
__global__ __launch_bounds__(128) void attn_h(
    const uint32_t* __restrict__ qkv2, uint32_t* __restrict__ out2)
{
    extern __shared__ uint32_t dsm[];
    auto Ksm = (uint32_t(*)[16][136])dsm;
    auto Vsm = (uint32_t(*)[32][68])(dsm + 2 * 16 * 136);
    uint32_t* Psm = dsm + 2 * 16 * 136 + 2 * 32 * 68;   // [4][32][36]

    const int tid  = threadIdx.x;
    const int w    = tid >> 5;
    const int lane = tid & 31;
    const int gid  = lane >> 2;
    const int tig  = lane & 3;
    const int h    = blockIdx.y;
    const int n0   = blockIdx.x * QB;

    const uint32_t* Qb = qkv2 + (size_t)(h * 16) * NSP;
    const uint32_t* Kb = qkv2 + (size_t)(128 + h * 16) * NSP;
    const uint32_t* Vb = qkv2 + (size_t)(256 + h * 16) * NSP;

    const int sp = tid >> 3;          // 0..15: K/V dim-pair row
    const int sc = (tid & 7) * 16;    // key word base (16 keys per thread)

    uint4 vr[4];
    auto ldg_V = [&](int j0) {
        #pragma unroll
        for (int p = 0; p < 4; ++p)
            vr[p] = *(const uint4*)(Vb + (size_t)sp * NSP + j0 + sc + 4 * p);
    };
    auto sts_V = [&](int b) {
        #pragma unroll
        for (int p = 0; p < 4; ++p) {
            const int kp = (sc >> 1) + 2 * p;
            Vsm[b][2 * sp][kp]         = prmt(vr[p].x, vr[p].y, 0x5410);
            Vsm[b][2 * sp + 1][kp]     = prmt(vr[p].x, vr[p].y, 0x7632);
            Vsm[b][2 * sp][kp + 1]     = prmt(vr[p].z, vr[p].w, 0x5410);
            Vsm[b][2 * sp + 1][kp + 1] = prmt(vr[p].z, vr[p].w, 0x7632);
        }
    };
    auto cp_K = [&](int b, int j0) {
        const uint32_t* src = Kb + (size_t)sp * NSP + j0 + sc;
        #pragma unroll
        for (int p = 0; p < 4; ++p)
            cp16(smem_u32(&Ksm[b][sp][sc + 4 * p]), src + 4 * p);
        CP_COMMIT();
    };

    cp_K(0, 0);
    ldg_V(0);

    // Q fragments (pre-scaled half2 dim-pairs)
    uint32_t qa[2][2][4];
    #pragma unroll
    for (int u = 0; u < 2; ++u) {
        const int rl = n0 + w * 32 + u * 16 + gid;
        #pragma unroll
        for (int ks = 0; ks < 2; ++ks) {
            const uint32_t* q0 = Qb + (size_t)(ks * 8 + tig) * NSP + rl;
            const uint32_t* q1 = Qb + (size_t)(ks * 8 + tig + 4) * NSP + rl;
            qa[u][ks][0] = q0[0];
            qa[u][ks][1] = q0[8];
            qa[u][ks][2] = q1[0];
            qa[u][ks][3] = q1[8];
        }
    }

    float o[2][4][4] = {};
    float lacc[2][4] = {};
    const uint32_t ONES = 0x3C003C00u;

    const int NT = NSP / KB;   // 32 tiles
    for (int t = 0; t < NT; ++t) {
        const int b = t & 1;
        sts_V(b);
        CP_WAIT0();
        __syncthreads();
        if (t + 1 < NT) { cp_K(b ^ 1, (t + 1) * KB); ldg_V((t + 1) * KB); }

        // fused per 16-key chunk: QK MMA -> ex2.f16x2 (reg P) -> l/PV MMA
        #pragma unroll
        for (int kc = 0; kc < 8; ++kc) {
            float s[2][2][4] = {};    // [u][ntp][4]
            #pragma unroll
            for (int ks = 0; ks < 2; ++ks) {
                #pragma unroll
                for (int ntp = 0; ntp < 2; ++ntp) {
                    uint32_t b0 = Ksm[b][ks * 8 + tig][kc * 16 + ntp * 8 + gid];
                    uint32_t b1 = Ksm[b][ks * 8 + tig + 4][kc * 16 + ntp * 8 + gid];
                    mmaf16(s[0][ntp], qa[0][ks], b0, b1);
                    mmaf16(s[1][ntp], qa[1][ks], b0, b1);
                }
            }
            uint32_t aP[2][4];
            #pragma unroll
            for (int u = 0; u < 2; ++u) {
                aP[u][0] = ex2h2(packh2(s[u][0][0], s[u][0][1]));
                aP[u][1] = ex2h2(packh2(s[u][0][2], s[u][0][3]));
                aP[u][2] = ex2h2(packh2(s[u][1][0], s[u][1][1]));
                aP[u][3] = ex2h2(packh2(s[u][1][2], s[u][1][3]));
                mmaf16(lacc[u], aP[u], ONES, ONES);
            }
            #pragma unroll
            for (int nt = 0; nt < 4; ++nt) {
                uint32_t b0 = Vsm[b][nt * 8 + gid][kc * 8 + tig];
                uint32_t b1 = Vsm[b][nt * 8 + gid][kc * 8 + tig + 4];
                mmaf16(o[0][nt], aP[0], b0, b1);
                mmaf16(o[1][nt], aP[1], b0, b1);
            }
        }
    }

    const float il[2][2] = { {1.f / lacc[0][0], 1.f / lacc[0][2]},
                             {1.f / lacc[1][0], 1.f / lacc[1][2]} };

    __syncthreads();
    float* Pf = (float*)(Psm + w * 32 * 36);
    #pragma unroll
    for (int u = 0; u < 2; ++u)
        #pragma unroll
        for (int nt = 0; nt < 4; ++nt) {
            const int c0 = nt * 8 + 2 * tig;
            *(float2*)&Pf[(u * 16 + gid) * 36 + c0] =
                make_float2(o[u][nt][0] * il[u][0], o[u][nt][1] * il[u][0]);
            *(float2*)&Pf[(u * 16 + gid + 8) * 36 + c0] =
                make_float2(o[u][nt][2] * il[u][1], o[u][nt][3] * il[u][1]);
        }
    __syncwarp();

    const float* Pr = Pf + lane * 36;
    uint32_t* ob = out2 + (size_t)(h * 16) * NSP + n0 + w * 32 + lane;
    #pragma unroll
    for (int dp = 0; dp < 16; ++dp) {
        float2 v = *(const float2*)&Pr[2 * dp];
        ob[(size_t)dp * NSP] = packh2(v.x, v.y);
    }
}

// ---------------------------------------------------------------------------
extern "C" void kernel_launch(void* const* d_in, const int* in_sizes, int n_in,
                              void* d_out, int out_size)
{
    const float* x      = (const float*)d_in[0];
    const float* w_dw   = (const float*)d_in[1];
    const float* b_dw   = (const float*)d_in[2];
    const float* w_qkv  = (const float*)d_in[3];
    const float* b_qkv  = (const float*)d_in[4];
    const float* w_proj = (const float*)d_in[5];
    const float* b_proj = (const float*)d_in[6];
    float* outp = (float*)d_out;

    uint32_t *py2, *pqkv2, *patt2, *pwq2, *pwp2;
    cudaGetSymbolAddress((void**)&py2,   g_y2);
    cudaGetSymbolAddress((void**)&pqkv2, g_qkv2);
    cudaGetSymbolAddress((void**)&patt2, g_att2);
    cudaGetSymbolAddress((void**)&pwq2,  g_wq2);
    cudaGetSymbolAddress((void**)&pwp2,  g_wp2);

    const float SC = 0.17677669529663688f * 1.4426950408889634f; // hd^-0.5 * log2e
    const int GEMM_SMEM = (64 * 132 + 128 * 72) * 4;                       // 70656 B
    const int ATTN_SMEM = (2 * 16 * 136 + 2 * 32 * 68 + 4 * 32 * 36) * 4;  // 53248 B
    static int smem_set = 0;
    if (!smem_set) {
        cudaFuncSetAttribute(gemm_h2<true>,  cudaFuncAttributeMaxDynamicSharedMemorySize, GEMM_SMEM);
        cudaFuncSetAttribute(gemm_h2<false>, cudaFuncAttributeMaxDynamicSharedMemorySize, GEMM_SMEM);
        cudaFuncSetAttribute(attn_h,         cudaFuncAttributeMaxDynamicSharedMemorySize, ATTN_SMEM);
        smem_set = 1;
    }

    conv_in_kernel<<<148, 256>>>(x, w_dw, b_dw, py2, w_qkv, w_proj, pwq2, pwp2);
    gemm_h2<true><<<dim3(NSP / 64, (3 * CCH) / 64), 128, GEMM_SMEM>>>(
        pwq2, py2, b_qkv, pqkv2, NSP, SC);
    attn_h<<<dim3(NSP / QB, NHEADS), 128, ATTN_SMEM>>>(pqkv2, patt2);
    gemm_h2<false><<<dim3(NSP / 64, CCH / 64), 128, GEMM_SMEM>>>(
        pwp2, patt2, b_proj, outp, NSP, 1.0f);
}

// round 12
// speedup vs baseline: 1.0342x; 1.0342x over previous
#include <cuda_runtime.h>
#include <cuda_fp16.h>
#include <cstdint>

#define NSP 4096      // H*W*D = 16^3
#define CCH 256
#define NHEADS 8
#define HD 32
#define QB 256
#define KB 128

// scratch, all channel-pair-interleaved half2 words: X2[c/2][n] = half2(X[c],X[c+1])
__device__ uint32_t g_y2[(CCH / 2) * NSP];
__device__ uint32_t g_qkv2[(3 * CCH / 2) * NSP];   // Q rows pre-scaled by hd^-.5*log2e
__device__ uint32_t g_att2[(CCH / 2) * NSP];
// weights as half2 k-pairs: W2[m][k/2]
__device__ uint32_t g_wq2[3 * CCH * (CCH / 2)];
__device__ uint32_t g_wp2[CCH * (CCH / 2)];

// ---------------------------------------------------------------------------
__device__ __forceinline__ uint32_t smem_u32(const void* p) {
    uint32_t a;
    asm("{ .reg .u64 t; cvta.to.shared.u64 t, %1; cvt.u32.u64 %0, t; }" : "=r"(a) : "l"(p));
    return a;
}
__device__ __forceinline__ void cp16(uint32_t saddr, const void* g) {
    asm volatile("cp.async.cg.shared.global [%0], [%1], 16;" :: "r"(saddr), "l"(g));
}
#define CP_COMMIT() asm volatile("cp.async.commit_group;" ::: "memory")
#define CP_WAIT0()  asm volatile("cp.async.wait_group 0;" ::: "memory")

__device__ __forceinline__ void mmaf16(float c[4], const uint32_t a[4],
                                       uint32_t b0, uint32_t b1) {
    asm("mma.sync.aligned.m16n8k16.row.col.f32.f16.f16.f32 "
        "{%0,%1,%2,%3}, {%4,%5,%6,%7}, {%8,%9}, {%0,%1,%2,%3};"
        : "+f"(c[0]), "+f"(c[1]), "+f"(c[2]), "+f"(c[3])
        : "r"(a[0]), "r"(a[1]), "r"(a[2]), "r"(a[3]), "r"(b0), "r"(b1));
}
__device__ __forceinline__ uint32_t packh2(float lo, float hi) {
    __half2 h = __float22half2_rn(make_float2(lo, hi));
    return *reinterpret_cast<uint32_t*>(&h);
}
__device__ __forceinline__ uint32_t ex2h2(uint32_t x) {
    uint32_t r; asm("ex2.approx.f16x2 %0, %1;" : "=r"(r) : "r"(x)); return r;
}
__device__ __forceinline__ uint32_t prmt(uint32_t a, uint32_t b, uint32_t sel) {
    uint32_t d; asm("prmt.b32 %0, %1, %2, %3;" : "=r"(d) : "r"(a), "r"(b), "r"(sel)); return d;
}

// ---------------------------------------------------------------------------
// Kernel 1: depthwise conv + InstanceNorm (blocks 0..127, 2 channels each),
// PLUS weight fp32->half2 pre-conversion on spare blocks 128..147.
// ---------------------------------------------------------------------------
__global__ __launch_bounds__(256) void conv_in_kernel(
    const float* __restrict__ x, const float* __restrict__ wdw,
    const float* __restrict__ bdw, uint32_t* __restrict__ y2,
    const float* __restrict__ wq, const float* __restrict__ wp,
    uint32_t* __restrict__ wq2, uint32_t* __restrict__ wp2)
{
    const int tid = threadIdx.x;

    if (blockIdx.x >= 128) {
        const int idx = (blockIdx.x - 128) * 256 + tid;
        const int STR = 20 * 256;
        const int NQ = 3 * CCH * (CCH / 2);
        for (int i = idx; i < NQ; i += STR) {
            float2 f = *(const float2*)(wq + 2 * i);
            wq2[i] = packh2(f.x, f.y);
        }
        const int NP = CCH * (CCH / 2);
        for (int i = idx; i < NP; i += STR) {
            float2 f = *(const float2*)(wp + 2 * i);
            wp2[i] = packh2(f.x, f.y);
        }
        return;
    }

    const int cp = blockIdx.x;       // channel pair
    __shared__ float xs[NSP];
    __shared__ float red[512];

    const int w  = tid >> 4;
    const int dd = tid & 15;

    float prev[16];
    float out[16];

    for (int s = 0; s < 2; ++s) {
        const int c = 2 * cp + s;
        __syncthreads();
        const float4* xg = (const float4*)(x + (size_t)c * NSP);
        float4* xs4 = (float4*)xs;
        #pragma unroll
        for (int i = 0; i < 4; ++i) xs4[tid + 256 * i] = xg[tid + 256 * i];

        float wr[27];
        #pragma unroll
        for (int i = 0; i < 27; ++i) wr[i] = wdw[c * 27 + i];
        const float bias = bdw[c];
        __syncthreads();

        float sm = 0.f, s2 = 0.f;
        for (int hh = 0; hh < 16; ++hh) {
            float acc = bias;
            #pragma unroll
            for (int i = 0; i < 3; ++i) {
                int ih = hh + i - 1;
                if ((unsigned)ih < 16u) {
                    #pragma unroll
                    for (int j = 0; j < 3; ++j) {
                        int iw = w + j - 1;
                        if ((unsigned)iw < 16u) {
                            #pragma unroll
                            for (int k = 0; k < 3; ++k) {
                                int id = dd + k - 1;
                                if ((unsigned)id < 16u)
                                    acc = fmaf(xs[ih * 256 + iw * 16 + id], wr[i * 9 + j * 3 + k], acc);
                            }
                        }
                    }
                }
            }
            out[hh] = acc;
            sm += acc;
            s2 = fmaf(acc, acc, s2);
        }

        red[tid] = sm; red[256 + tid] = s2;
        __syncthreads();
        for (int st = 128; st > 0; st >>= 1) {
            if (tid < st) { red[tid] += red[tid + st]; red[256 + tid] += red[256 + tid + st]; }
            __syncthreads();
        }
        const float mean = red[0] * (1.0f / NSP);
        const float var  = red[256] * (1.0f / NSP) - mean * mean;
        const float rs   = rsqrtf(var + 1e-5f);

        if (s == 0) {
            for (int hh = 0; hh < 16; ++hh) prev[hh] = (out[hh] - mean) * rs;
        } else {
            for (int hh = 0; hh < 16; ++hh)
                y2[(size_t)cp * NSP + hh * 256 + tid] = packh2(prev[hh], (out[hh] - mean) * rs);
        }
    }
}

// ---------------------------------------------------------------------------
// Kernel 2/4: fp16 GEMM, BM=64, BN=64, full K=256 single-stage, 128 threads
// (4 warps, 2m x 2n). Both A (pre-converted weights) and B staged by cp.async.
// smem words: As[64][132] + Bs[128][72] = 70656 B.
// ---------------------------------------------------------------------------
template<bool HOUT>
__global__ __launch_bounds__(128) void gemm_h2(
    const uint32_t* __restrict__ A2, const uint32_t* __restrict__ B2,
    const float* __restrict__ bias, void* __restrict__ Cout,
    int N, float qsc)
{
    extern __shared__ uint32_t gsm[];
    auto As = (uint32_t(*)[132])gsm;              // [64][132]
    auto Bs = (uint32_t(*)[72])(gsm + 64 * 132);  // [128][72]

    const int tid  = threadIdx.x;
    const int w    = tid >> 5;
    const int lane = tid & 31;
    const int gid  = lane >> 2;
    const int tig  = lane & 3;
    const int wm   = w >> 1;
    const int wn   = w & 1;
    const int bm   = blockIdx.y * 64;
    const int bn   = blockIdx.x * 64;

    {
        const int r = tid >> 1, hf = tid & 1;
        const uint32_t* ar = A2 + (size_t)(bm + r) * 128 + hf * 64;
        #pragma unroll
        for (int p = 0; p < 16; ++p)
            cp16(smem_u32(&As[r][hf * 64 + p * 4]), ar + p * 4);
    }
    {
        const uint32_t* br = B2 + (size_t)tid * N + bn;
        #pragma unroll
        for (int p = 0; p < 16; ++p)
            cp16(smem_u32(&Bs[tid][p * 4]), br + p * 4);
    }
    CP_COMMIT();
    CP_WAIT0();
    __syncthreads();

    float acc[2][4][4] = {};
    #pragma unroll
    for (int ks = 0; ks < 16; ++ks) {
        uint32_t a[2][4];
        #pragma unroll
        for (int u = 0; u < 2; ++u) {
            const int mb = wm * 32 + u * 16 + gid;
            a[u][0] = As[mb][ks * 8 + tig];
            a[u][1] = As[mb + 8][ks * 8 + tig];
            a[u][2] = As[mb][ks * 8 + tig + 4];
            a[u][3] = As[mb + 8][ks * 8 + tig + 4];
        }
        #pragma unroll
        for (int nt = 0; nt < 4; ++nt) {
            const int col = wn * 32 + nt * 8 + gid;
            uint32_t b0 = Bs[ks * 8 + tig][col];
            uint32_t b1 = Bs[ks * 8 + tig + 4][col];
            mmaf16(acc[0][nt], a[0], b0, b1);
            mmaf16(acc[1][nt], a[1], b0, b1);
        }
    }
    __syncthreads();

    if (HOUT) {
        const float sc = (bm < 256) ? qsc : 1.0f;
        uint32_t* Cs32 = gsm;            // [64][36] words (72 halves/row)
        #pragma unroll
        for (int u = 0; u < 2; ++u) {
            const int r0 = wm * 32 + u * 16 + gid;
            const float bv0 = bias[bm + r0];
            const float bv1 = bias[bm + r0 + 8];
            #pragma unroll
            for (int nt = 0; nt < 4; ++nt) {
                const int wc = wn * 16 + nt * 4 + tig;
                Cs32[r0 * 36 + wc]       = packh2((acc[u][nt][0] + bv0) * sc,
                                                  (acc[u][nt][1] + bv0) * sc);
                Cs32[(r0 + 8) * 36 + wc] = packh2((acc[u][nt][2] + bv1) * sc,
                                                  (acc[u][nt][3] + bv1) * sc);
            }
        }
        __syncthreads();
        const unsigned short* Ch = (const unsigned short*)gsm;
        uint32_t* C2 = (uint32_t*)Cout;
        const int n  = tid & 63;
        const int rg = tid >> 6;
        #pragma unroll
        for (int p = 0; p < 16; ++p) {
            const int r = rg * 16 + p;
            uint32_t lo = Ch[(2 * r) * 72 + n];
            uint32_t hi = Ch[(2 * r + 1) * 72 + n];
            C2[(size_t)((bm >> 1) + r) * N + bn + n] = lo | (hi << 16);
        }
    } else {
        float* C = (float*)Cout;
        #pragma unroll
        for (int u = 0; u < 2; ++u) {
            const int m0 = bm + wm * 32 + u * 16 + gid;
            const float bv0 = bias[m0];
            const float bv1 = bias[m0 + 8];
            #pragma unroll
            for (int nt = 0; nt < 4; ++nt) {
                const int n = bn + wn * 32 + nt * 8 + tig * 2;
                *(float2*)(C + (size_t)m0 * N + n) =
                    make_float2(acc[u][nt][0] + bv0, acc[u][nt][1] + bv0);
                *(float2*)(C + (size_t)(m0 + 8) * N + n) =
                    make_float2(acc[u][nt][2] + bv1, acc[u][nt][3] + bv1);
            }
        }
    }
}

// ---------------------------------------------------------------------------
// Kernel 3: fp16 flash attention (round-10 verified config): QB=256, 8 warps,
// grid (16, 8) = 128 CTAs. P in registers (QK C-frag == PV A-frag),
// ex2.approx.f16x2, l via ones-MMA. KB=128 keys/tile (32 tiles).
// smem words: Ksm[2][16][136] + Vsm[2][32][68] + Psm[8][32][36].
// ---------------------------------------------------------------------------
__global__ __launch_bounds__(256) void attn_h(
    const uint32_t* __restrict__ qkv2, uint32_t* __restrict__ out2)
{
    extern __shared__ uint32_t dsm[];
    auto Ksm = (uint32_t(*)[16][136])dsm;
    auto Vsm = (uint32_t(*)[32][68])(dsm + 2 * 16 * 136);
    uint32_t* Psm = dsm + 2 * 16 * 136 + 2 * 32 * 68;   // [8][32][36]

    const int tid  = threadIdx.x;
    const int w    = tid >> 5;
    const int lane = tid & 31;
    const int gid  = lane >> 2;
    const int tig  = lane & 3;
    const int h    = blockIdx.y;
    const int n0   = blockIdx.x * QB;

    const uint32_t* Qb = qkv2 + (size_t)(h * 16) * NSP;
    const uint32_t* Kb = qkv2 + (size_t)(128 + h * 16) * NSP;
    const uint32_t* Vb = qkv2 + (size_t)(256 + h * 16) * NSP;

    const int sp = tid >> 4;          // 0..15: K row / V dim-pair
    const int sc = (tid & 15) * 8;    // K col base / V key base

    uint4 vr0, vr1;
    auto ldg_V = [&](int j0) {
        vr0 = *(const uint4*)(Vb + (size_t)sp * NSP + j0 + sc);
        vr1 = *(const uint4*)(Vb + (size_t)sp * NSP + j0 + sc + 4);
    };
    auto sts_V = [&](int b) {
        const int kp = sc >> 1;
        Vsm[b][2 * sp][kp]         = prmt(vr0.x, vr0.y, 0x5410);
        Vsm[b][2 * sp + 1][kp]     = prmt(vr0.x, vr0.y, 0x7632);
        Vsm[b][2 * sp][kp + 1]     = prmt(vr0.z, vr0.w, 0x5410);
        Vsm[b][2 * sp + 1][kp + 1] = prmt(vr0.z, vr0.w, 0x7632);
        Vsm[b][2 * sp][kp + 2]     = prmt(vr1.x, vr1.y, 0x5410);
        Vsm[b][2 * sp + 1][kp + 2] = prmt(vr1.x, vr1.y, 0x7632);
        Vsm[b][2 * sp][kp + 3]     = prmt(vr1.z, vr1.w, 0x5410);
        Vsm[b][2 * sp + 1][kp + 3] = prmt(vr1.z, vr1.w, 0x7632);
    };
    auto cp_K = [&](int b, int j0) {
        const uint32_t* src = Kb + (size_t)sp * NSP + j0 + sc;
        cp16(smem_u32(&Ksm[b][sp][sc]), src);
        cp16(smem_u32(&Ksm[b][sp][sc + 4]), src + 4);
        CP_COMMIT();
    };

    cp_K(0, 0);
    ldg_V(0);

    // Q fragments (pre-scaled half2 dim-pairs)
    uint32_t qa[2][2][4];
    #pragma unroll
    for (int u = 0; u < 2; ++u) {
        const int rl = n0 + w * 32 + u * 16 + gid;
        #pragma unroll
        for (int ks = 0; ks < 2; ++ks) {
            const uint32_t* q0 = Qb + (size_t)(ks * 8 + tig) * NSP + rl;
            const uint32_t* q1 = Qb + (size_t)(ks * 8 + tig + 4) * NSP + rl;
            qa[u][ks][0] = q0[0];
            qa[u][ks][1] = q0[8];
            qa[u][ks][2] = q1[0];
            qa[u][ks][3] = q1[8];
        }
    }

    float o[2][4][4] = {};
    float lacc[2][4] = {};
    const uint32_t ONES = 0x3C003C00u;

    const int NT = NSP / KB;   // 32 tiles
    for (int t = 0; t < NT; ++t) {
        const int b = t & 1;
        sts_V(b);
        CP_WAIT0();
        __syncthreads();
        if (t + 1 < NT) { cp_K(b ^ 1, (t + 1) * KB); ldg_V((t + 1) * KB); }

        // fused per 16-key chunk: QK MMA -> ex2.f16x2 (reg P) -> l/PV MMA
        #pragma unroll
        for (int kc = 0; kc < 8; ++kc) {
            float s[2][2][4] = {};    // [u][ntp][4]
            #pragma unroll
            for (int ks = 0; ks < 2; ++ks) {
                #pragma unroll
                for (int ntp = 0; ntp < 2; ++ntp) {
                    uint32_t b0 = Ksm[b][ks * 8 + tig][kc * 16 + ntp * 8 + gid];
                    uint32_t b1 = Ksm[b][ks * 8 + tig + 4][kc * 16 + ntp * 8 + gid];
                    mmaf16(s[0][ntp], qa[0][ks], b0, b1);
                    mmaf16(s[1][ntp], qa[1][ks], b0, b1);
                }
            }
            uint32_t aP[2][4];
            #pragma unroll
            for (int u = 0; u < 2; ++u) {
                aP[u][0] = ex2h2(packh2(s[u][0][0], s[u][0][1]));
                aP[u][1] = ex2h2(packh2(s[u][0][2], s[u][0][3]));
                aP[u][2] = ex2h2(packh2(s[u][1][0], s[u][1][1]));
                aP[u][3] = ex2h2(packh2(s[u][1][2], s[u][1][3]));
                mmaf16(lacc[u], aP[u], ONES, ONES);
            }
            #pragma unroll
            for (int nt = 0; nt < 4; ++nt) {
                uint32_t b0 = Vsm[b][nt * 8 + gid][kc * 8 + tig];
                uint32_t b1 = Vsm[b][nt * 8 + gid][kc * 8 + tig + 4];
                mmaf16(o[0][nt], aP[0], b0, b1);
                mmaf16(o[1][nt], aP[1], b0, b1);
            }
        }
    }

    const float il[2][2] = { {1.f / lacc[0][0], 1.f / lacc[0][2]},
                             {1.f / lacc[1][0], 1.f / lacc[1][2]} };

    __syncthreads();
    float* Pf = (float*)(Psm + w * 32 * 36);
    #pragma unroll
    for (int u = 0; u < 2; ++u)
        #pragma unroll
        for (int nt = 0; nt < 4; ++nt) {
            const int c0 = nt * 8 + 2 * tig;
            *(float2*)&Pf[(u * 16 + gid) * 36 + c0] =
                make_float2(o[u][nt][0] * il[u][0], o[u][nt][1] * il[u][0]);
            *(float2*)&Pf[(u * 16 + gid + 8) * 36 + c0] =
                make_float2(o[u][nt][2] * il[u][1], o[u][nt][3] * il[u][1]);
        }
    __syncwarp();

    const float* Pr = Pf + lane * 36;
    uint32_t* ob = out2 + (size_t)(h * 16) * NSP + n0 + w * 32 + lane;
    #pragma unroll
    for (int dp = 0; dp < 16; ++dp) {
        float2 v = *(const float2*)&Pr[2 * dp];
        ob[(size_t)dp * NSP] = packh2(v.x, v.y);
    }
}

// ---------------------------------------------------------------------------
extern "C" void kernel_launch(void* const* d_in, const int* in_sizes, int n_in,
                              void* d_out, int out_size)
{
    const float* x      = (const float*)d_in[0];
    const float* w_dw   = (const float*)d_in[1];
    const float* b_dw   = (const float*)d_in[2];
    const float* w_qkv  = (const float*)d_in[3];
    const float* b_qkv  = (const float*)d_in[4];
    const float* w_proj = (const float*)d_in[5];
    const float* b_proj = (const float*)d_in[6];
    float* outp = (float*)d_out;

    uint32_t *py2, *pqkv2, *patt2, *pwq2, *pwp2;
    cudaGetSymbolAddress((void**)&py2,   g_y2);
    cudaGetSymbolAddress((void**)&pqkv2, g_qkv2);
    cudaGetSymbolAddress((void**)&patt2, g_att2);
    cudaGetSymbolAddress((void**)&pwq2,  g_wq2);
    cudaGetSymbolAddress((void**)&pwp2,  g_wp2);

    const float SC = 0.17677669529663688f * 1.4426950408889634f; // hd^-0.5 * log2e
    const int GEMM_SMEM = (64 * 132 + 128 * 72) * 4;                       // 70656 B
    const int ATTN_SMEM = (2 * 16 * 136 + 2 * 32 * 68 + 8 * 32 * 36) * 4;  // 71680 B
    static int smem_set = 0;
    if (!smem_set) {
        cudaFuncSetAttribute(gemm_h2<true>,  cudaFuncAttributeMaxDynamicSharedMemorySize, GEMM_SMEM);
        cudaFuncSetAttribute(gemm_h2<false>, cudaFuncAttributeMaxDynamicSharedMemorySize, GEMM_SMEM);
        cudaFuncSetAttribute(attn_h,         cudaFuncAttributeMaxDynamicSharedMemorySize, ATTN_SMEM);
        smem_set = 1;
    }

    conv_in_kernel<<<148, 256>>>(x, w_dw, b_dw, py2, w_qkv, w_proj, pwq2, pwp2);
    gemm_h2<true><<<dim3(NSP / 64, (3 * CCH) / 64), 128, GEMM_SMEM>>>(
        pwq2, py2, b_qkv, pqkv2, NSP, SC);
    attn_h<<<dim3(NSP / QB, NHEADS), 256, ATTN_SMEM>>>(pqkv2, patt2);
    gemm_h2<false><<<dim3(NSP / 64, CCH / 64), 128, GEMM_SMEM>>>(
        pwp2, patt2, b_proj, outp, NSP, 1.0f);
}

// round 13
// speedup vs baseline: 1.1174x; 1.0805x over previous
#include <cuda_runtime.h>
#include <cuda_fp16.h>
#include <cstdint>

#define NSP 4096      // H*W*D = 16^3
#define CCH 256
#define NHEADS 8
#define HD 32
#define QB 256
#define KB 128

// scratch, all channel-pair-interleaved half2 words: X2[c/2][n] = half2(X[c],X[c+1])
__device__ uint32_t g_y2[(CCH / 2) * NSP];
__device__ uint32_t g_qkv2[(3 * CCH / 2) * NSP];   // Q rows pre-scaled by hd^-.5*log2e
__device__ uint32_t g_att2[(CCH / 2) * NSP];
// weights as half2 k-pairs: W2[m][k/2]
__device__ uint32_t g_wq2[3 * CCH * (CCH / 2)];
__device__ uint32_t g_wp2[CCH * (CCH / 2)];

// ---------------------------------------------------------------------------
__device__ __forceinline__ uint32_t smem_u32(const void* p) {
    uint32_t a;
    asm("{ .reg .u64 t; cvta.to.shared.u64 t, %1; cvt.u32.u64 %0, t; }" : "=r"(a) : "l"(p));
    return a;
}
__device__ __forceinline__ void cp16(uint32_t saddr, const void* g) {
    asm volatile("cp.async.cg.shared.global [%0], [%1], 16;" :: "r"(saddr), "l"(g));
}
#define CP_COMMIT() asm volatile("cp.async.commit_group;" ::: "memory")
#define CP_WAIT0()  asm volatile("cp.async.wait_group 0;" ::: "memory")

__device__ __forceinline__ void mmaf16(float c[4], const uint32_t a[4],
                                       uint32_t b0, uint32_t b1) {
    asm("mma.sync.aligned.m16n8k16.row.col.f32.f16.f16.f32 "
        "{%0,%1,%2,%3}, {%4,%5,%6,%7}, {%8,%9}, {%0,%1,%2,%3};"
        : "+f"(c[0]), "+f"(c[1]), "+f"(c[2]), "+f"(c[3])
        : "r"(a[0]), "r"(a[1]), "r"(a[2]), "r"(a[3]), "r"(b0), "r"(b1));
}
__device__ __forceinline__ uint32_t packh2(float lo, float hi) {
    __half2 h = __float22half2_rn(make_float2(lo, hi));
    return *reinterpret_cast<uint32_t*>(&h);
}
__device__ __forceinline__ uint32_t ex2h2(uint32_t x) {
    uint32_t r; asm("ex2.approx.f16x2 %0, %1;" : "=r"(r) : "r"(x)); return r;
}
__device__ __forceinline__ uint32_t prmt(uint32_t a, uint32_t b, uint32_t sel) {
    uint32_t d; asm("prmt.b32 %0, %1, %2, %3;" : "=r"(d) : "r"(a), "r"(b), "r"(sel)); return d;
}

// ---------------------------------------------------------------------------
// Kernel 1: depthwise conv + InstanceNorm (blocks 0..127, 2 channels each),
// PLUS weight fp32->half2 pre-conversion on spare blocks 128..147.
// ---------------------------------------------------------------------------
__global__ __launch_bounds__(256) void conv_in_kernel(
    const float* __restrict__ x, const float* __restrict__ wdw,
    const float* __restrict__ bdw, uint32_t* __restrict__ y2,
    const float* __restrict__ wq, const float* __restrict__ wp,
    uint32_t* __restrict__ wq2, uint32_t* __restrict__ wp2)
{
    const int tid = threadIdx.x;

    if (blockIdx.x >= 128) {
        const int idx = (blockIdx.x - 128) * 256 + tid;
        const int STR = 20 * 256;
        const int NQ = 3 * CCH * (CCH / 2);
        for (int i = idx; i < NQ; i += STR) {
            float2 f = *(const float2*)(wq + 2 * i);
            wq2[i] = packh2(f.x, f.y);
        }
        const int NP = CCH * (CCH / 2);
        for (int i = idx; i < NP; i += STR) {
            float2 f = *(const float2*)(wp + 2 * i);
            wp2[i] = packh2(f.x, f.y);
        }
        return;
    }

    const int cp = blockIdx.x;       // channel pair
    __shared__ float xs[NSP];
    __shared__ float red[512];

    const int w  = tid >> 4;
    const int dd = tid & 15;

    float prev[16];
    float out[16];

    for (int s = 0; s < 2; ++s) {
        const int c = 2 * cp + s;
        __syncthreads();
        const float4* xg = (const float4*)(x + (size_t)c * NSP);
        float4* xs4 = (float4*)xs;
        #pragma unroll
        for (int i = 0; i < 4; ++i) xs4[tid + 256 * i] = xg[tid + 256 * i];

        float wr[27];
        #pragma unroll
        for (int i = 0; i < 27; ++i) wr[i] = wdw[c * 27 + i];
        const float bias = bdw[c];
        __syncthreads();

        float sm = 0.f, s2 = 0.f;
        for (int hh = 0; hh < 16; ++hh) {
            float acc = bias;
            #pragma unroll
            for (int i = 0; i < 3; ++i) {
                int ih = hh + i - 1;
                if ((unsigned)ih < 16u) {
                    #pragma unroll
                    for (int j = 0; j < 3; ++j) {
                        int iw = w + j - 1;
                        if ((unsigned)iw < 16u) {
                            #pragma unroll
                            for (int k = 0; k < 3; ++k) {
                                int id = dd + k - 1;
                                if ((unsigned)id < 16u)
                                    acc = fmaf(xs[ih * 256 + iw * 16 + id], wr[i * 9 + j * 3 + k], acc);
                            }
                        }
                    }
                }
            }
            out[hh] = acc;
            sm += acc;
            s2 = fmaf(acc, acc, s2);
        }

        red[tid] = sm; red[256 + tid] = s2;
        __syncthreads();
        for (int st = 128; st > 0; st >>= 1) {
            if (tid < st) { red[tid] += red[tid + st]; red[256 + tid] += red[256 + tid + st]; }
            __syncthreads();
        }
        const float mean = red[0] * (1.0f / NSP);
        const float var  = red[256] * (1.0f / NSP) - mean * mean;
        const float rs   = rsqrtf(var + 1e-5f);

        if (s == 0) {
            for (int hh = 0; hh < 16; ++hh) prev[hh] = (out[hh] - mean) * rs;
        } else {
            for (int hh = 0; hh < 16; ++hh)
                y2[(size_t)cp * NSP + hh * 256 + tid] = packh2(prev[hh], (out[hh] - mean) * rs);
        }
    }
}

// ---------------------------------------------------------------------------
// Kernel 2 (qkv): fp16 GEMM, BM=128, BN=64, 256 threads (8 warps, 4m x 2n),
// single-stage full K=256, all cp.async from pre-converted weights.
// Output half2 pair-interleaved with per-row scale (qsc for rows<256).
// smem words: As[128][132] + Bs[128][72] = 26112 -> 104448 B (2 CTAs/SM).
// ---------------------------------------------------------------------------
__global__ __launch_bounds__(256) void gemm_h3(
    const uint32_t* __restrict__ A2, const uint32_t* __restrict__ B2,
    const float* __restrict__ bias, uint32_t* __restrict__ C2,
    int N, float qsc)
{
    extern __shared__ uint32_t gsm[];
    auto As = (uint32_t(*)[132])gsm;               // [128][132]
    auto Bs = (uint32_t(*)[72])(gsm + 128 * 132);  // [128][72]

    const int tid  = threadIdx.x;
    const int w    = tid >> 5;
    const int lane = tid & 31;
    const int gid  = lane >> 2;
    const int tig  = lane & 3;
    const int wm   = w >> 1;           // 0..3
    const int wn   = w & 1;
    const int bm   = blockIdx.y * 128;
    const int bn   = blockIdx.x * 64;

    {
        const int r = tid >> 1, hf = tid & 1;
        const uint32_t* ar = A2 + (size_t)(bm + r) * 128 + hf * 64;
        #pragma unroll
        for (int p = 0; p < 16; ++p)
            cp16(smem_u32(&As[r][hf * 64 + p * 4]), ar + p * 4);
        const uint32_t* br = B2 + (size_t)r * N + bn + hf * 32;
        #pragma unroll
        for (int p = 0; p < 8; ++p)
            cp16(smem_u32(&Bs[r][hf * 32 + p * 4]), br + p * 4);
    }
    CP_COMMIT();
    CP_WAIT0();
    __syncthreads();

    float acc[2][4][4] = {};
    #pragma unroll
    for (int ks = 0; ks < 16; ++ks) {
        uint32_t a[2][4];
        #pragma unroll
        for (int u = 0; u < 2; ++u) {
            const int mb = wm * 32 + u * 16 + gid;
            a[u][0] = As[mb][ks * 8 + tig];
            a[u][1] = As[mb + 8][ks * 8 + tig];
            a[u][2] = As[mb][ks * 8 + tig + 4];
            a[u][3] = As[mb + 8][ks * 8 + tig + 4];
        }
        #pragma unroll
        for (int nt = 0; nt < 4; ++nt) {
            const int col = wn * 32 + nt * 8 + gid;
            uint32_t b0 = Bs[ks * 8 + tig][col];
            uint32_t b1 = Bs[ks * 8 + tig + 4][col];
            mmaf16(acc[0][nt], a[0], b0, b1);
            mmaf16(acc[1][nt], a[1], b0, b1);
        }
    }
    __syncthreads();

    // half2 pair-interleaved epilogue via smem restage: [128][36] words
    const float sc = (bm < 256) ? qsc : 1.0f;
    uint32_t* Cs32 = gsm;
    #pragma unroll
    for (int u = 0; u < 2; ++u) {
        const int r0 = wm * 32 + u * 16 + gid;
        const float bv0 = bias[bm + r0];
        const float bv1 = bias[bm + r0 + 8];
        #pragma unroll
        for (int nt = 0; nt < 4; ++nt) {
            const int wc = wn * 16 + nt * 4 + tig;
            Cs32[r0 * 36 + wc]       = packh2((acc[u][nt][0] + bv0) * sc,
                                              (acc[u][nt][1] + bv0) * sc);
            Cs32[(r0 + 8) * 36 + wc] = packh2((acc[u][nt][2] + bv1) * sc,
                                              (acc[u][nt][3] + bv1) * sc);
        }
    }
    __syncthreads();
    const unsigned short* Ch = (const unsigned short*)gsm;
    const int n  = tid & 63;
    const int rg = tid >> 6;            // 0..3
    #pragma unroll
    for (int p = 0; p < 16; ++p) {
        const int r = rg * 16 + p;      // row-pairs 0..63
        uint32_t lo = Ch[(2 * r) * 72 + n];
        uint32_t hi = Ch[(2 * r + 1) * 72 + n];
        C2[(size_t)((bm >> 1) + r) * N + bn + n] = lo | (hi << 16);
    }
}

// ---------------------------------------------------------------------------
// Kernel 4 (proj): round-11/12 verified gemm (BM=64, BN=64, 128 threads,
// fp32 output). Measured 10.8 us.
// ---------------------------------------------------------------------------
__global__ __launch_bounds__(128) void gemm_h2(
    const uint32_t* __restrict__ A2, const uint32_t* __restrict__ B2,
    const float* __restrict__ bias, float* __restrict__ C,
    int N)
{
    extern __shared__ uint32_t gsm[];
    auto As = (uint32_t(*)[132])gsm;              // [64][132]
    auto Bs = (uint32_t(*)[72])(gsm + 64 * 132);  // [128][72]

    const int tid  = threadIdx.x;
    const int w    = tid >> 5;
    const int lane = tid & 31;
    const int gid  = lane >> 2;
    const int tig  = lane & 3;
    const int wm   = w >> 1;
    const int wn   = w & 1;
    const int bm   = blockIdx.y * 64;
    const int bn   = blockIdx.x * 64;

    {
        const int r = tid >> 1, hf = tid & 1;
        const uint32_t* ar = A2 + (size_t)(bm + r) * 128 + hf * 64;
        #pragma unroll
        for (int p = 0; p < 16; ++p)
            cp16(smem_u32(&As[r][hf * 64 + p * 4]), ar + p * 4);
    }
    {
        const uint32_t* br = B2 + (size_t)tid * N + bn;
        #pragma unroll
        for (int p = 0; p < 16; ++p)
            cp16(smem_u32(&Bs[tid][p * 4]), br + p * 4);
    }
    CP_COMMIT();
    CP_WAIT0();
    __syncthreads();

    float acc[2][4][4] = {};
    #pragma unroll
    for (int ks = 0; ks < 16; ++ks) {
        uint32_t a[2][4];
        #pragma unroll
        for (int u = 0; u < 2; ++u) {
            const int mb = wm * 32 + u * 16 + gid;
            a[u][0] = As[mb][ks * 8 + tig];
            a[u][1] = As[mb + 8][ks * 8 + tig];
            a[u][2] = As[mb][ks * 8 + tig + 4];
            a[u][3] = As[mb + 8][ks * 8 + tig + 4];
        }
        #pragma unroll
        for (int nt = 0; nt < 4; ++nt) {
            const int col = wn * 32 + nt * 8 + gid;
            uint32_t b0 = Bs[ks * 8 + tig][col];
            uint32_t b1 = Bs[ks * 8 + tig + 4][col];
            mmaf16(acc[0][nt], a[0], b0, b1);
            mmaf16(acc[1][nt], a[1], b0, b1);
        }
    }

    #pragma unroll
    for (int u = 0; u < 2; ++u) {
        const int m0 = bm + wm * 32 + u * 16 + gid;
        const float bv0 = bias[m0];
        const float bv1 = bias[m0 + 8];
        #pragma unroll
        for (int nt = 0; nt < 4; ++nt) {
            const int n = bn + wn * 32 + nt * 8 + tig * 2;
            *(float2*)(C + (size_t)m0 * N + n) =
                make_float2(acc[u][nt][0] + bv0, acc[u][nt][1] + bv0);
            *(float2*)(C + (size_t)(m0 + 8) * N + n) =
                make_float2(acc[u][nt][2] + bv1, acc[u][nt][3] + bv1);
        }
    }
}

// ---------------------------------------------------------------------------
// Kernel 3: fp16 flash attention, 512 threads (16 warps, 16 q-rows each),
// QB=256, grid (16, 8) = 128 CTAs -> 4 warps/SMSP for latency hiding.
// P in registers (QK C-frag == PV A-frag), ex2.approx.f16x2, l via ones-MMA.
// smem words: Ksm[2][16][136] + Vsm[2][32][68] + Psm[16][16][36] = 71680 B.
// ---------------------------------------------------------------------------
__global__ __launch_bounds__(512) void attn_h(
    const uint32_t* __restrict__ qkv2, uint32_t* __restrict__ out2)
{
    extern __shared__ uint32_t dsm[];
    auto Ksm = (uint32_t(*)[16][136])dsm;
    auto Vsm = (uint32_t(*)[32][68])(dsm + 2 * 16 * 136);
    uint32_t* Psm = dsm + 2 * 16 * 136 + 2 * 32 * 68;   // [16][16][36]

    const int tid  = threadIdx.x;
    const int w    = tid >> 5;        // 0..15
    const int lane = tid & 31;
    const int gid  = lane >> 2;
    const int tig  = lane & 3;
    const int h    = blockIdx.y;
    const int n0   = blockIdx.x * QB;

    const uint32_t* Qb = qkv2 + (size_t)(h * 16) * NSP;
    const uint32_t* Kb = qkv2 + (size_t)(128 + h * 16) * NSP;
    const uint32_t* Vb = qkv2 + (size_t)(256 + h * 16) * NSP;

    const int sp = tid >> 5;          // 0..15: K row / V dim-pair
    const int sc = (lane) * 4;        // word offset (4 words per thread)

    uint4 vr;
    auto ldg_V = [&](int j0) {
        vr = *(const uint4*)(Vb + (size_t)sp * NSP + j0 + sc);
    };
    auto sts_V = [&](int b) {
        const int kp = sc >> 1;
        Vsm[b][2 * sp][kp]         = prmt(vr.x, vr.y, 0x5410);
        Vsm[b][2 * sp + 1][kp]     = prmt(vr.x, vr.y, 0x7632);
        Vsm[b][2 * sp][kp + 1]     = prmt(vr.z, vr.w, 0x5410);
        Vsm[b][2 * sp + 1][kp + 1] = prmt(vr.z, vr.w, 0x7632);
    };
    auto cp_K = [&](int b, int j0) {
        cp16(smem_u32(&Ksm[b][sp][sc]), Kb + (size_t)sp * NSP + j0 + sc);
        CP_COMMIT();
    };

    cp_K(0, 0);
    ldg_V(0);

    // Q fragments (pre-scaled half2 dim-pairs), one m16 block per warp
    uint32_t qa[2][4];
    {
        const int rl = n0 + w * 16 + gid;
        #pragma unroll
        for (int ks = 0; ks < 2; ++ks) {
            const uint32_t* q0 = Qb + (size_t)(ks * 8 + tig) * NSP + rl;
            const uint32_t* q1 = Qb + (size_t)(ks * 8 + tig + 4) * NSP + rl;
            qa[ks][0] = q0[0];
            qa[ks][1] = q0[8];
            qa[ks][2] = q1[0];
            qa[ks][3] = q1[8];
        }
    }

    float o[4][4] = {};
    float lacc[4] = {};
    const uint32_t ONES = 0x3C003C00u;

    const int NT = NSP / KB;   // 32 tiles
    for (int t = 0; t < NT; ++t) {
        const int b = t & 1;
        sts_V(b);
        CP_WAIT0();
        __syncthreads();
        if (t + 1 < NT) { cp_K(b ^ 1, (t + 1) * KB); ldg_V((t + 1) * KB); }

        // fused per 16-key chunk: QK MMA -> ex2.f16x2 (reg P) -> l/PV MMA
        #pragma unroll
        for (int kc = 0; kc < 8; ++kc) {
            float s[2][4] = {};    // [ntp][4]
            #pragma unroll
            for (int ks = 0; ks < 2; ++ks) {
                #pragma unroll
                for (int ntp = 0; ntp < 2; ++ntp) {
                    uint32_t b0 = Ksm[b][ks * 8 + tig][kc * 16 + ntp * 8 + gid];
                    uint32_t b1 = Ksm[b][ks * 8 + tig + 4][kc * 16 + ntp * 8 + gid];
                    mmaf16(s[ntp], qa[ks], b0, b1);
                }
            }
            uint32_t aP[4];
            aP[0] = ex2h2(packh2(s[0][0], s[0][1]));
            aP[1] = ex2h2(packh2(s[0][2], s[0][3]));
            aP[2] = ex2h2(packh2(s[1][0], s[1][1]));
            aP[3] = ex2h2(packh2(s[1][2], s[1][3]));
            mmaf16(lacc, aP, ONES, ONES);
            #pragma unroll
            for (int nt = 0; nt < 4; ++nt) {
                uint32_t b0 = Vsm[b][nt * 8 + gid][kc * 8 + tig];
                uint32_t b1 = Vsm[b][nt * 8 + gid][kc * 8 + tig + 4];
                mmaf16(o[nt], aP, b0, b1);
            }
        }
    }

    const float il0 = 1.f / lacc[0];
    const float il1 = 1.f / lacc[2];

    __syncthreads();
    float* Pf = (float*)(Psm + w * 16 * 36);
    #pragma unroll
    for (int nt = 0; nt < 4; ++nt) {
        const int c0 = nt * 8 + 2 * tig;
        *(float2*)&Pf[gid * 36 + c0] =
            make_float2(o[nt][0] * il0, o[nt][1] * il0);
        *(float2*)&Pf[(gid + 8) * 36 + c0] =
            make_float2(o[nt][2] * il1, o[nt][3] * il1);
    }
    __syncwarp();

    const int r    = lane & 15;
    const int half = lane >> 4;
    const float* Pr = Pf + r * 36 + half * 16;
    uint32_t* ob = out2 + (size_t)(h * 16 + half * 8) * NSP + n0 + w * 16 + r;
    #pragma unroll
    for (int dp = 0; dp < 8; ++dp) {
        float2 v = *(const float2*)&Pr[2 * dp];
        ob[(size_t)dp * NSP] = packh2(v.x, v.y);
    }
}

// ---------------------------------------------------------------------------
extern "C" void kernel_launch(void* const* d_in, const int* in_sizes, int n_in,
                              void* d_out, int out_size)
{
    const float* x      = (const float*)d_in[0];
    const float* w_dw   = (const float*)d_in[1];
    const float* b_dw   = (const float*)d_in[2];
    const float* w_qkv  = (const float*)d_in[3];
    const float* b_qkv  = (const float*)d_in[4];
    const float* w_proj = (const float*)d_in[5];
    const float* b_proj = (const float*)d_in[6];
    float* outp = (float*)d_out;

    uint32_t *py2, *pqkv2, *patt2, *pwq2, *pwp2;
    cudaGetSymbolAddress((void**)&py2,   g_y2);
    cudaGetSymbolAddress((void**)&pqkv2, g_qkv2);
    cudaGetSymbolAddress((void**)&patt2, g_att2);
    cudaGetSymbolAddress((void**)&pwq2,  g_wq2);
    cudaGetSymbolAddress((void**)&pwp2,  g_wp2);

    const float SC = 0.17677669529663688f * 1.4426950408889634f; // hd^-0.5 * log2e
    const int G3_SMEM   = (128 * 132 + 128 * 72) * 4;                      // 104448 B
    const int G2_SMEM   = (64 * 132 + 128 * 72) * 4;                       // 70656 B
    const int ATTN_SMEM = (2 * 16 * 136 + 2 * 32 * 68 + 16 * 16 * 36) * 4; // 71680 B
    static int smem_set = 0;
    if (!smem_set) {
        cudaFuncSetAttribute(gemm_h3, cudaFuncAttributeMaxDynamicSharedMemorySize, G3_SMEM);
        cudaFuncSetAttribute(gemm_h2, cudaFuncAttributeMaxDynamicSharedMemorySize, G2_SMEM);
        cudaFuncSetAttribute(attn_h,  cudaFuncAttributeMaxDynamicSharedMemorySize, ATTN_SMEM);
        smem_set = 1;
    }

    conv_in_kernel<<<148, 256>>>(x, w_dw, b_dw, py2, w_qkv, w_proj, pwq2, pwp2);
    gemm_h3<<<dim3(NSP / 64, (3 * CCH) / 128), 256, G3_SMEM>>>(
        pwq2, py2, b_qkv, pqkv2, NSP, SC);
    attn_h<<<dim3(NSP / QB, NHEADS), 512, ATTN_SMEM>>>(pqkv2, patt2);
    gemm_h2<<<dim3(NSP / 64, CCH / 64), 128, G2_SMEM>>>(
        pwp2, patt2, b_proj, outp, NSP);
}

// round 14
// speedup vs baseline: 1.2120x; 1.0847x over previous
#include <cuda_runtime.h>
#include <cuda_fp16.h>
#include <cstdint>

#define NSP 4096      // H*W*D = 16^3
#define CCH 256
#define NHEADS 8
#define HD 32
#define QB 256
#define KB 128

// scratch, all channel-pair-interleaved half2 words: X2[c/2][n] = half2(X[c],X[c+1])
__device__ uint32_t g_y2[(CCH / 2) * NSP];
__device__ uint32_t g_qkv2[(3 * CCH / 2) * NSP];   // Q rows pre-scaled by hd^-.5*log2e
__device__ uint32_t g_att2[(CCH / 2) * NSP];
// weights as half2 k-pairs: W2[m][k/2]
__device__ uint32_t g_wq2[3 * CCH * (CCH / 2)];
__device__ uint32_t g_wp2[CCH * (CCH / 2)];

// ---------------------------------------------------------------------------
__device__ __forceinline__ uint32_t smem_u32(const void* p) {
    uint32_t a;
    asm("{ .reg .u64 t; cvta.to.shared.u64 t, %1; cvt.u32.u64 %0, t; }" : "=r"(a) : "l"(p));
    return a;
}
__device__ __forceinline__ void cp16(uint32_t saddr, const void* g) {
    asm volatile("cp.async.cg.shared.global [%0], [%1], 16;" :: "r"(saddr), "l"(g));
}
#define CP_COMMIT() asm volatile("cp.async.commit_group;" ::: "memory")
#define CP_WAIT0()  asm volatile("cp.async.wait_group 0;" ::: "memory")

__device__ __forceinline__ void mmaf16(float c[4], const uint32_t a[4],
                                       uint32_t b0, uint32_t b1) {
    asm("mma.sync.aligned.m16n8k16.row.col.f32.f16.f16.f32 "
        "{%0,%1,%2,%3}, {%4,%5,%6,%7}, {%8,%9}, {%0,%1,%2,%3};"
        : "+f"(c[0]), "+f"(c[1]), "+f"(c[2]), "+f"(c[3])
        : "r"(a[0]), "r"(a[1]), "r"(a[2]), "r"(a[3]), "r"(b0), "r"(b1));
}
__device__ __forceinline__ uint32_t packh2(float lo, float hi) {
    __half2 h = __float22half2_rn(make_float2(lo, hi));
    return *reinterpret_cast<uint32_t*>(&h);
}
__device__ __forceinline__ uint32_t ex2h2(uint32_t x) {
    uint32_t r; asm("ex2.approx.f16x2 %0, %1;" : "=r"(r) : "r"(x)); return r;
}
__device__ __forceinline__ uint32_t prmt(uint32_t a, uint32_t b, uint32_t sel) {
    uint32_t d; asm("prmt.b32 %0, %1, %2, %3;" : "=r"(d) : "r"(a), "r"(b), "r"(sel)); return d;
}

// ---------------------------------------------------------------------------
// Kernel 1: depthwise 3x3x3 conv + bias + InstanceNorm, ONE channel per CTA
// (grid 256 + 20 weight-prep blocks). Warp-shfl reductions (2 syncs/CTA).
// Output: 16-bit stores into pair-interleaved half2 words (race-free bytes).
// ---------------------------------------------------------------------------
__global__ __launch_bounds__(256) void conv_in_kernel(
    const float* __restrict__ x, const float* __restrict__ wdw,
    const float* __restrict__ bdw, unsigned short* __restrict__ y2h,
    const float* __restrict__ wq, const float* __restrict__ wp,
    uint32_t* __restrict__ wq2, uint32_t* __restrict__ wp2)
{
    const int tid = threadIdx.x;

    if (blockIdx.x >= 256) {
        const int idx = (blockIdx.x - 256) * 256 + tid;
        const int STR = 20 * 256;
        const int NQ = 3 * CCH * (CCH / 2);
        for (int i = idx; i < NQ; i += STR) {
            float2 f = *(const float2*)(wq + 2 * i);
            wq2[i] = packh2(f.x, f.y);
        }
        const int NP = CCH * (CCH / 2);
        for (int i = idx; i < NP; i += STR) {
            float2 f = *(const float2*)(wp + 2 * i);
            wp2[i] = packh2(f.x, f.y);
        }
        return;
    }

    const int c = blockIdx.x;
    __shared__ float xs[NSP];
    __shared__ float red[16];

    const int w  = tid >> 4;
    const int dd = tid & 15;
    const int wid  = tid >> 5;
    const int lane = tid & 31;

    {
        const float4* xg = (const float4*)(x + (size_t)c * NSP);
        float4* xs4 = (float4*)xs;
        #pragma unroll
        for (int i = 0; i < 4; ++i) xs4[tid + 256 * i] = xg[tid + 256 * i];
    }
    float wr[27];
    #pragma unroll
    for (int i = 0; i < 27; ++i) wr[i] = wdw[c * 27 + i];
    const float bias = bdw[c];
    __syncthreads();

    float out[16];
    float sm = 0.f, s2 = 0.f;
    for (int hh = 0; hh < 16; ++hh) {
        float acc = bias;
        #pragma unroll
        for (int i = 0; i < 3; ++i) {
            int ih = hh + i - 1;
            if ((unsigned)ih < 16u) {
                #pragma unroll
                for (int j = 0; j < 3; ++j) {
                    int iw = w + j - 1;
                    if ((unsigned)iw < 16u) {
                        #pragma unroll
                        for (int k = 0; k < 3; ++k) {
                            int id = dd + k - 1;
                            if ((unsigned)id < 16u)
                                acc = fmaf(xs[ih * 256 + iw * 16 + id], wr[i * 9 + j * 3 + k], acc);
                        }
                    }
                }
            }
        }
        out[hh] = acc;
        sm += acc;
        s2 = fmaf(acc, acc, s2);
    }

    // warp-level reduction, then cross-warp via 16-float smem
    #pragma unroll
    for (int o = 16; o > 0; o >>= 1) {
        sm += __shfl_xor_sync(0xFFFFFFFFu, sm, o);
        s2 += __shfl_xor_sync(0xFFFFFFFFu, s2, o);
    }
    if (lane == 0) { red[wid] = sm; red[8 + wid] = s2; }
    __syncthreads();
    float ts = 0.f, t2 = 0.f;
    #pragma unroll
    for (int i = 0; i < 8; ++i) { ts += red[i]; t2 += red[8 + i]; }

    const float mean = ts * (1.0f / NSP);
    const float var  = t2 * (1.0f / NSP) - mean * mean;
    const float rs   = rsqrtf(var + 1e-5f);

    unsigned short* yb = y2h + ((size_t)(c >> 1) * NSP) * 2 + (c & 1);
    for (int hh = 0; hh < 16; ++hh) {
        __half hv = __float2half_rn((out[hh] - mean) * rs);
        yb[(size_t)(hh * 256 + tid) * 2] = *reinterpret_cast<unsigned short*>(&hv);
    }
}

// ---------------------------------------------------------------------------
// Kernel 2 (qkv): fp16 GEMM, BM=128, BN=64, 256 threads (8 warps, 4m x 2n),
// single-stage full K=256, all cp.async from pre-converted weights.
// Output half2 pair-interleaved with per-row scale (qsc for rows<256).
// smem words: As[128][132] + Bs[128][72] -> 104448 B.
// ---------------------------------------------------------------------------
__global__ __launch_bounds__(256) void gemm_h3(
    const uint32_t* __restrict__ A2, const uint32_t* __restrict__ B2,
    const float* __restrict__ bias, uint32_t* __restrict__ C2,
    int N, float qsc)
{
    extern __shared__ uint32_t gsm[];
    auto As = (uint32_t(*)[132])gsm;               // [128][132]
    auto Bs = (uint32_t(*)[72])(gsm + 128 * 132);  // [128][72]

    const int tid  = threadIdx.x;
    const int w    = tid >> 5;
    const int lane = tid & 31;
    const int gid  = lane >> 2;
    const int tig  = lane & 3;
    const int wm   = w >> 1;           // 0..3
    const int wn   = w & 1;
    const int bm   = blockIdx.y * 128;
    const int bn   = blockIdx.x * 64;

    {
        const int r = tid >> 1, hf = tid & 1;
        const uint32_t* ar = A2 + (size_t)(bm + r) * 128 + hf * 64;
        #pragma unroll
        for (int p = 0; p < 16; ++p)
            cp16(smem_u32(&As[r][hf * 64 + p * 4]), ar + p * 4);
        const uint32_t* br = B2 + (size_t)r * N + bn + hf * 32;
        #pragma unroll
        for (int p = 0; p < 8; ++p)
            cp16(smem_u32(&Bs[r][hf * 32 + p * 4]), br + p * 4);
    }
    CP_COMMIT();
    CP_WAIT0();
    __syncthreads();

    float acc[2][4][4] = {};
    #pragma unroll
    for (int ks = 0; ks < 16; ++ks) {
        uint32_t a[2][4];
        #pragma unroll
        for (int u = 0; u < 2; ++u) {
            const int mb = wm * 32 + u * 16 + gid;
            a[u][0] = As[mb][ks * 8 + tig];
            a[u][1] = As[mb + 8][ks * 8 + tig];
            a[u][2] = As[mb][ks * 8 + tig + 4];
            a[u][3] = As[mb + 8][ks * 8 + tig + 4];
        }
        #pragma unroll
        for (int nt = 0; nt < 4; ++nt) {
            const int col = wn * 32 + nt * 8 + gid;
            uint32_t b0 = Bs[ks * 8 + tig][col];
            uint32_t b1 = Bs[ks * 8 + tig + 4][col];
            mmaf16(acc[0][nt], a[0], b0, b1);
            mmaf16(acc[1][nt], a[1], b0, b1);
        }
    }
    __syncthreads();

    // half2 pair-interleaved epilogue via smem restage: [128][36] words
    const float sc = (bm < 256) ? qsc : 1.0f;
    uint32_t* Cs32 = gsm;
    #pragma unroll
    for (int u = 0; u < 2; ++u) {
        const int r0 = wm * 32 + u * 16 + gid;
        const float bv0 = bias[bm + r0];
        const float bv1 = bias[bm + r0 + 8];
        #pragma unroll
        for (int nt = 0; nt < 4; ++nt) {
            const int wc = wn * 16 + nt * 4 + tig;
            Cs32[r0 * 36 + wc]       = packh2((acc[u][nt][0] + bv0) * sc,
                                              (acc[u][nt][1] + bv0) * sc);
            Cs32[(r0 + 8) * 36 + wc] = packh2((acc[u][nt][2] + bv1) * sc,
                                              (acc[u][nt][3] + bv1) * sc);
        }
    }
    __syncthreads();
    const unsigned short* Ch = (const unsigned short*)gsm;
    const int n  = tid & 63;
    const int rg = tid >> 6;            // 0..3
    #pragma unroll
    for (int p = 0; p < 16; ++p) {
        const int r = rg * 16 + p;      // row-pairs 0..63
        uint32_t lo = Ch[(2 * r) * 72 + n];
        uint32_t hi = Ch[(2 * r + 1) * 72 + n];
        C2[(size_t)((bm >> 1) + r) * N + bn + n] = lo | (hi << 16);
    }
}

// ---------------------------------------------------------------------------
// Kernel 4 (proj): fp16 GEMM, BM=64, BN=64, 256 threads (8 warps, 2m x 4n),
// single-stage full K=256, all cp.async, fp32 output.
// smem words: As[64][132] + Bs[128][72] = 70656 B. Grid 256 CTAs.
// ---------------------------------------------------------------------------
__global__ __launch_bounds__(256) void gemm_p(
    const uint32_t* __restrict__ A2, const uint32_t* __restrict__ B2,
    const float* __restrict__ bias, float* __restrict__ C,
    int N)
{
    extern __shared__ uint32_t gsm[];
    auto As = (uint32_t(*)[132])gsm;              // [64][132]
    auto Bs = (uint32_t(*)[72])(gsm + 64 * 132);  // [128][72]

    const int tid  = threadIdx.x;
    const int w    = tid >> 5;
    const int lane = tid & 31;
    const int gid  = lane >> 2;
    const int tig  = lane & 3;
    const int wm   = w >> 2;           // 0..1 (32 rows each)
    const int wn   = w & 3;            // 0..3 (16 cols each)
    const int bm   = blockIdx.y * 64;
    const int bn   = blockIdx.x * 64;

    {
        const int r = tid >> 2, q = tid & 3;
        const uint32_t* ar = A2 + (size_t)(bm + r) * 128 + q * 32;
        #pragma unroll
        for (int p = 0; p < 8; ++p)
            cp16(smem_u32(&As[r][q * 32 + p * 4]), ar + p * 4);
        const int r2 = tid >> 1, hf = tid & 1;
        const uint32_t* br = B2 + (size_t)r2 * N + bn + hf * 32;
        #pragma unroll
        for (int p = 0; p < 8; ++p)
            cp16(smem_u32(&Bs[r2][hf * 32 + p * 4]), br + p * 4);
    }
    CP_COMMIT();
    CP_WAIT0();
    __syncthreads();

    float acc[2][2][4] = {};
    #pragma unroll
    for (int ks = 0; ks < 16; ++ks) {
        uint32_t a[2][4];
        #pragma unroll
        for (int u = 0; u < 2; ++u) {
            const int mb = wm * 32 + u * 16 + gid;
            a[u][0] = As[mb][ks * 8 + tig];
            a[u][1] = As[mb + 8][ks * 8 + tig];
            a[u][2] = As[mb][ks * 8 + tig + 4];
            a[u][3] = As[mb + 8][ks * 8 + tig + 4];
        }
        #pragma unroll
        for (int nt = 0; nt < 2; ++nt) {
            const int col = wn * 16 + nt * 8 + gid;
            uint32_t b0 = Bs[ks * 8 + tig][col];
            uint32_t b1 = Bs[ks * 8 + tig + 4][col];
            mmaf16(acc[0][nt], a[0], b0, b1);
            mmaf16(acc[1][nt], a[1], b0, b1);
        }
    }

    #pragma unroll
    for (int u = 0; u < 2; ++u) {
        const int m0 = bm + wm * 32 + u * 16 + gid;
        const float bv0 = bias[m0];
        const float bv1 = bias[m0 + 8];
        #pragma unroll
        for (int nt = 0; nt < 2; ++nt) {
            const int n = bn + wn * 16 + nt * 8 + tig * 2;
            *(float2*)(C + (size_t)m0 * N + n) =
                make_float2(acc[u][nt][0] + bv0, acc[u][nt][1] + bv0);
            *(float2*)(C + (size_t)(m0 + 8) * N + n) =
                make_float2(acc[u][nt][2] + bv1, acc[u][nt][3] + bv1);
        }
    }
}

// ---------------------------------------------------------------------------
// Kernel 3: fp16 flash attention (round-13 verified): 512 threads (16 warps,
// 16 q-rows each), QB=256, grid (16, 8) = 128 CTAs. P in registers,
// ex2.approx.f16x2, l via ones-MMA. KB=128 (32 tiles).
// smem words: Ksm[2][16][136] + Vsm[2][32][68] + Psm[16][16][36].
// ---------------------------------------------------------------------------
__global__ __launch_bounds__(512) void attn_h(
    const uint32_t* __restrict__ qkv2, uint32_t* __restrict__ out2)
{
    extern __shared__ uint32_t dsm[];
    auto Ksm = (uint32_t(*)[16][136])dsm;
    auto Vsm = (uint32_t(*)[32][68])(dsm + 2 * 16 * 136);
    uint32_t* Psm = dsm + 2 * 16 * 136 + 2 * 32 * 68;   // [16][16][36]

    const int tid  = threadIdx.x;
    const int w    = tid >> 5;        // 0..15
    const int lane = tid & 31;
    const int gid  = lane >> 2;
    const int tig  = lane & 3;
    const int h    = blockIdx.y;
    const int n0   = blockIdx.x * QB;

    const uint32_t* Qb = qkv2 + (size_t)(h * 16) * NSP;
    const uint32_t* Kb = qkv2 + (size_t)(128 + h * 16) * NSP;
    const uint32_t* Vb = qkv2 + (size_t)(256 + h * 16) * NSP;

    const int sp = tid >> 5;          // 0..15: K row / V dim-pair
    const int sc = (lane) * 4;        // word offset (4 words per thread)

    uint4 vr;
    auto ldg_V = [&](int j0) {
        vr = *(const uint4*)(Vb + (size_t)sp * NSP + j0 + sc);
    };
    auto sts_V = [&](int b) {
        const int kp = sc >> 1;
        Vsm[b][2 * sp][kp]         = prmt(vr.x, vr.y, 0x5410);
        Vsm[b][2 * sp + 1][kp]     = prmt(vr.x, vr.y, 0x7632);
        Vsm[b][2 * sp][kp + 1]     = prmt(vr.z, vr.w, 0x5410);
        Vsm[b][2 * sp + 1][kp + 1] = prmt(vr.z, vr.w, 0x7632);
    };
    auto cp_K = [&](int b, int j0) {
        cp16(smem_u32(&Ksm[b][sp][sc]), Kb + (size_t)sp * NSP + j0 + sc);
        CP_COMMIT();
    };

    cp_K(0, 0);
    ldg_V(0);

    // Q fragments (pre-scaled half2 dim-pairs), one m16 block per warp
    uint32_t qa[2][4];
    {
        const int rl = n0 + w * 16 + gid;
        #pragma unroll
        for (int ks = 0; ks < 2; ++ks) {
            const uint32_t* q0 = Qb + (size_t)(ks * 8 + tig) * NSP + rl;
            const uint32_t* q1 = Qb + (size_t)(ks * 8 + tig + 4) * NSP + rl;
            qa[ks][0] = q0[0];
            qa[ks][1] = q0[8];
            qa[ks][2] = q1[0];
            qa[ks][3] = q1[8];
        }
    }

    float o[4][4] = {};
    float lacc[4] = {};
    const uint32_t ONES = 0x3C003C00u;

    const int NT = NSP / KB;   // 32 tiles
    for (int t = 0; t < NT; ++t) {
        const int b = t & 1;
        sts_V(b);
        CP_WAIT0();
        __syncthreads();
        if (t + 1 < NT) { cp_K(b ^ 1, (t + 1) * KB); ldg_V((t + 1) * KB); }

        // fused per 16-key chunk: QK MMA -> ex2.f16x2 (reg P) -> l/PV MMA
        #pragma unroll
        for (int kc = 0; kc < 8; ++kc) {
            float s[2][4] = {};    // [ntp][4]
            #pragma unroll
            for (int ks = 0; ks < 2; ++ks) {
                #pragma unroll
                for (int ntp = 0; ntp < 2; ++ntp) {
                    uint32_t b0 = Ksm[b][ks * 8 + tig][kc * 16 + ntp * 8 + gid];
                    uint32_t b1 = Ksm[b][ks * 8 + tig + 4][kc * 16 + ntp * 8 + gid];
                    mmaf16(s[ntp], qa[ks], b0, b1);
                }
            }
            uint32_t aP[4];
            aP[0] = ex2h2(packh2(s[0][0], s[0][1]));
            aP[1] = ex2h2(packh2(s[0][2], s[0][3]));
            aP[2] = ex2h2(packh2(s[1][0], s[1][1]));
            aP[3] = ex2h2(packh2(s[1][2], s[1][3]));
            mmaf16(lacc, aP, ONES, ONES);
            #pragma unroll
            for (int nt = 0; nt < 4; ++nt) {
                uint32_t b0 = Vsm[b][nt * 8 + gid][kc * 8 + tig];
                uint32_t b1 = Vsm[b][nt * 8 + gid][kc * 8 + tig + 4];
                mmaf16(o[nt], aP, b0, b1);
            }
        }
    }

    const float il0 = 1.f / lacc[0];
    const float il1 = 1.f / lacc[2];

    __syncthreads();
    float* Pf = (float*)(Psm + w * 16 * 36);
    #pragma unroll
    for (int nt = 0; nt < 4; ++nt) {
        const int c0 = nt * 8 + 2 * tig;
        *(float2*)&Pf[gid * 36 + c0] =
            make_float2(o[nt][0] * il0, o[nt][1] * il0);
        *(float2*)&Pf[(gid + 8) * 36 + c0] =
            make_float2(o[nt][2] * il1, o[nt][3] * il1);
    }
    __syncwarp();

    const int r    = lane & 15;
    const int half = lane >> 4;
    const float* Pr = Pf + r * 36 + half * 16;
    uint32_t* ob = out2 + (size_t)(h * 16 + half * 8) * NSP + n0 + w * 16 + r;
    #pragma unroll
    for (int dp = 0; dp < 8; ++dp) {
        float2 v = *(const float2*)&Pr[2 * dp];
        ob[(size_t)dp * NSP] = packh2(v.x, v.y);
    }
}

// ---------------------------------------------------------------------------
extern "C" void kernel_launch(void* const* d_in, const int* in_sizes, int n_in,
                              void* d_out, int out_size)
{
    const float* x      = (const float*)d_in[0];
    const float* w_dw   = (const float*)d_in[1];
    const float* b_dw   = (const float*)d_in[2];
    const float* w_qkv  = (const float*)d_in[3];
    const float* b_qkv  = (const float*)d_in[4];
    const float* w_proj = (const float*)d_in[5];
    const float* b_proj = (const float*)d_in[6];
    float* outp = (float*)d_out;

    uint32_t *py2, *pqkv2, *patt2, *pwq2, *pwp2;
    cudaGetSymbolAddress((void**)&py2,   g_y2);
    cudaGetSymbolAddress((void**)&pqkv2, g_qkv2);
    cudaGetSymbolAddress((void**)&patt2, g_att2);
    cudaGetSymbolAddress((void**)&pwq2,  g_wq2);
    cudaGetSymbolAddress((void**)&pwp2,  g_wp2);

    const float SC = 0.17677669529663688f * 1.4426950408889634f; // hd^-0.5 * log2e
    const int G3_SMEM   = (128 * 132 + 128 * 72) * 4;                      // 104448 B
    const int GP_SMEM   = (64 * 132 + 128 * 72) * 4;                       // 70656 B
    const int ATTN_SMEM = (2 * 16 * 136 + 2 * 32 * 68 + 16 * 16 * 36) * 4; // 71680 B
    static int smem_set = 0;
    if (!smem_set) {
        cudaFuncSetAttribute(gemm_h3, cudaFuncAttributeMaxDynamicSharedMemorySize, G3_SMEM);
        cudaFuncSetAttribute(gemm_p,  cudaFuncAttributeMaxDynamicSharedMemorySize, GP_SMEM);
        cudaFuncSetAttribute(attn_h,  cudaFuncAttributeMaxDynamicSharedMemorySize, ATTN_SMEM);
        smem_set = 1;
    }

    conv_in_kernel<<<276, 256>>>(x, w_dw, b_dw, (unsigned short*)py2,
                                 w_qkv, w_proj, pwq2, pwp2);
    gemm_h3<<<dim3(NSP / 64, (3 * CCH) / 128), 256, G3_SMEM>>>(
        pwq2, py2, b_qkv, pqkv2, NSP, SC);
    attn_h<<<dim3(NSP / QB, NHEADS), 512, ATTN_SMEM>>>(pqkv2, patt2);
    gemm_p<<<dim3(NSP / 64, CCH / 64), 256, GP_SMEM>>>(
        pwp2, patt2, b_proj, outp, NSP);
}